// round 5
// baseline (speedup 1.0000x reference)
#include <cuda_runtime.h>
#include <cstdint>

#define B_TOTAL   4096
#define Z_TILE    32
#define NBLOCKS   (B_TOTAL / Z_TILE)   // 128
#define FEAT      832                  // 64*(1+3+9)
#define SROW      833                  // padded smem row
#define NPATH     15
#define KTOT      4096                 // (a,b) pairs
#define WROW      (NPATH * 64)         // 960 floats per k
#define WT_ELEMS  (KTOT * WROW)
#define OFF1      64
#define OFF2      256

// Transposed weights W_t[k][path][c]  (~15.7 MB device scratch)
__device__ float g_Wt[WT_ELEMS];

__global__ void wt_transpose_kernel(const float* __restrict__ w) {
    int o = blockIdx.x * 256 + threadIdx.x;
    if (o >= WT_ELEMS) return;
    int k = o / WROW;
    int r = o - k * WROW;       // p*64 + c
    int p = r >> 6;
    int c = r & 63;
    g_Wt[o] = w[p * 262144 + c * 4096 + k];
}

#define FMA2(acc, a, b) asm("fma.rn.f32x2 %0, %1, %2, %0;" : "+l"(acc) : "l"(a), "l"(b))

__device__ __forceinline__ unsigned long long dup2(float p) {
    unsigned long long d;
    unsigned int u = __float_as_uint(p);
    asm("mov.b64 %0, {%1, %2};" : "=l"(d) : "r"(u), "r"(u));
    return d;
}

__device__ __forceinline__ float2 unpk(unsigned long long v) {
    unsigned int lo, hi;
    asm("mov.b64 {%0, %1}, %2;" : "=r"(lo), "=r"(hi) : "l"(v));
    return make_float2(__uint_as_float(lo), __uint_as_float(hi));
}

template <int DIM>
__device__ __forceinline__ void do_path(const float* __restrict__ swc, const int pidx,
                                        const int w8,
                                        unsigned long long (*acc)[DIM],
                                        const float* __restrict__ P) {
    const ulonglong2* wp = reinterpret_cast<const ulonglong2*>(swc + pidx * 64 + w8);
    ulonglong2 wa = wp[0];   // c pairs (0,1),(2,3)
    ulonglong2 wb = wp[1];   // c pairs (4,5),(6,7)
#pragma unroll
    for (int u = 0; u < DIM; u++) {
        unsigned long long pd = dup2(P[u]);
        FMA2(acc[0][u], wa.x, pd);
        FMA2(acc[1][u], wa.y, pd);
        FMA2(acc[2][u], wb.x, pd);
        FMA2(acc[3][u], wb.y, pd);
    }
}

__global__ void __launch_bounds__(256, 1)
tp_kernel(const float* __restrict__ x1, const float* __restrict__ x2,
          float* __restrict__ out) {
    extern __shared__ float smem[];
    float* sA  = smem;                          // 32*833
    float* sB  = smem + Z_TILE * SROW;          // 32*833
    float* sW0 = smem + 2 * Z_TILE * SROW;      // 960
    float* sW1 = sW0 + WROW;                    // 960

    const int tid  = threadIdx.x;
    const int w8   = (tid >> 5) * 8;   // warp -> 8 output channels
    const int lane = tid & 31;         // lane -> z within tile
    const int z0   = blockIdx.x * Z_TILE;

    for (int r = 0; r < Z_TILE; r++) {
        const float* pa = x1 + (size_t)(z0 + r) * FEAT;
        const float* pb = x2 + (size_t)(z0 + r) * FEAT;
        for (int f = tid; f < FEAT; f += 256) {
            sA[r * SROW + f] = pa[f];
            sB[r * SROW + f] = pb[f];
        }
    }
    if (tid < 240) {
        float4 v = *reinterpret_cast<const float4*>(g_Wt + tid * 4);
        *reinterpret_cast<float4*>(sW0 + tid * 4) = v;
    }
    __syncthreads();

    const float* Az = sA + lane * SROW;
    const float* Bz = sB + lane * SROW;

    unsigned long long acc2[4][9], acc1[4][3], acc0[4][1];
#pragma unroll
    for (int j = 0; j < 4; j++) {
        acc0[j][0] = 0ull;
#pragma unroll
        for (int u = 0; u < 3; u++) acc1[j][u] = 0ull;
#pragma unroll
        for (int u = 0; u < 9; u++) acc2[j][u] = 0ull;
    }

    float* swc = sW0;
    float* swn = sW1;

#pragma unroll 1
    for (int a = 0; a < 64; a++) {
        const float aS = Az[a];
        float av[3], am[9];
#pragma unroll
        for (int i = 0; i < 3; i++) av[i] = Az[OFF1 + a * 3 + i];
#pragma unroll
        for (int i = 0; i < 9; i++) am[i] = Az[OFF2 + a * 9 + i];

#pragma unroll 1
        for (int b = 0; b < 64; b++) {
            const int k = a * 64 + b;
            const bool pre = (tid < 240) && (k + 1 < KTOT);
            float4 pf;
            if (pre) pf = *reinterpret_cast<const float4*>(g_Wt + (size_t)(k + 1) * WROW + tid * 4);

            const float bS = Bz[b];
            float bv[3], bm[9];
#pragma unroll
            for (int i = 0; i < 3; i++) bv[i] = Bz[OFF1 + b * 3 + i];
#pragma unroll
            for (int i = 0; i < 9; i++) bm[i] = Bz[OFF2 + b * 9 + i];

            float P[9];

            // p0: (0,0)->0
            P[0] = aS * bS;
            do_path<1>(swc, 0, w8, acc0, P);
            // p1: (0,1)->1
            P[0] = aS * bv[0]; P[1] = aS * bv[1]; P[2] = aS * bv[2];
            do_path<3>(swc, 1, w8, acc1, P);
            // p2: (0,2)->2
#pragma unroll
            for (int i = 0; i < 9; i++) P[i] = aS * bm[i];
            do_path<9>(swc, 2, w8, acc2, P);
            // p3: (1,0)->1
            P[0] = av[0] * bS; P[1] = av[1] * bS; P[2] = av[2] * bS;
            do_path<3>(swc, 3, w8, acc1, P);
            // p4: (1,1)->2 outer, u=3i+j
#pragma unroll
            for (int i = 0; i < 3; i++)
#pragma unroll
                for (int j = 0; j < 3; j++) P[3 * i + j] = av[i] * bv[j];
            do_path<9>(swc, 4, w8, acc2, P);
            // p5: (1,1)->0 dot
            P[0] = fmaf(av[2], bv[2], fmaf(av[1], bv[1], av[0] * bv[0]));
            do_path<1>(swc, 5, w8, acc0, P);
            // p6: (1,1)->1 cross
            P[0] = av[1] * bv[2] - av[2] * bv[1];
            P[1] = av[2] * bv[0] - av[0] * bv[2];
            P[2] = av[0] * bv[1] - av[1] * bv[0];
            do_path<3>(swc, 6, w8, acc1, P);
            // p7: (1,2)->1 k=1: P[e]=dot(av, bm_row_e)
#pragma unroll
            for (int e = 0; e < 3; e++)
                P[e] = fmaf(av[2], bm[3 * e + 2], fmaf(av[1], bm[3 * e + 1], av[0] * bm[3 * e]));
            do_path<3>(swc, 7, w8, acc1, P);
            // p8: (1,2)->2 eps: P[3e+g]=cross(av, bm_row_e)[g]
#pragma unroll
            for (int e = 0; e < 3; e++) {
                P[3 * e + 0] = av[1] * bm[3 * e + 2] - av[2] * bm[3 * e + 1];
                P[3 * e + 1] = av[2] * bm[3 * e + 0] - av[0] * bm[3 * e + 2];
                P[3 * e + 2] = av[0] * bm[3 * e + 1] - av[1] * bm[3 * e + 0];
            }
            do_path<9>(swc, 8, w8, acc2, P);
            // p9: (2,0)->2
#pragma unroll
            for (int i = 0; i < 9; i++) P[i] = am[i] * bS;
            do_path<9>(swc, 9, w8, acc2, P);
            // p10: (2,1)->1 k=1: P[d]=dot(am_row_d, bv)
#pragma unroll
            for (int d = 0; d < 3; d++)
                P[d] = fmaf(am[3 * d + 2], bv[2], fmaf(am[3 * d + 1], bv[1], am[3 * d] * bv[0]));
            do_path<3>(swc, 10, w8, acc1, P);
            // p11: (2,1)->2 eps: P[3d+g]=cross(am_row_d, bv)[g]
#pragma unroll
            for (int d = 0; d < 3; d++) {
                P[3 * d + 0] = am[3 * d + 1] * bv[2] - am[3 * d + 2] * bv[1];
                P[3 * d + 1] = am[3 * d + 2] * bv[0] - am[3 * d + 0] * bv[2];
                P[3 * d + 2] = am[3 * d + 0] * bv[1] - am[3 * d + 1] * bv[0];
            }
            do_path<9>(swc, 11, w8, acc2, P);
            // M[d][f] = dot(am_row_d, bm_row_f) shared by p12,p13,p14
            float M[9];
#pragma unroll
            for (int d = 0; d < 3; d++)
#pragma unroll
                for (int f = 0; f < 3; f++)
                    M[3 * d + f] = fmaf(am[3 * d + 2], bm[3 * f + 2],
                                   fmaf(am[3 * d + 1], bm[3 * f + 1],
                                        am[3 * d] * bm[3 * f]));
            // p12: (2,2)->2 k=1
            do_path<9>(swc, 12, w8, acc2, M);
            // p13: (2,2)->0 k=2 (Frobenius = trace(M))
            P[0] = M[0] + M[4] + M[8];
            do_path<1>(swc, 13, w8, acc0, P);
            // p14: (2,2)->1 eps k=1
            P[0] = M[5] - M[7];
            P[1] = M[6] - M[2];
            P[2] = M[1] - M[3];
            do_path<3>(swc, 14, w8, acc1, P);

            if (pre) *reinterpret_cast<float4*>(swn + tid * 4) = pf;
            __syncthreads();
            float* t = swc; swc = swn; swn = t;
        }
    }

    const int zg = z0 + lane;
    float* po = out + (size_t)zg * FEAT;
#pragma unroll
    for (int j = 0; j < 4; j++) {
        const int c0 = w8 + 2 * j;
        float2 f0 = unpk(acc0[j][0]);
        po[c0] = f0.x;
        po[c0 + 1] = f0.y;
#pragma unroll
        for (int u = 0; u < 3; u++) {
            float2 f = unpk(acc1[j][u]);
            po[OFF1 + c0 * 3 + u] = f.x;
            po[OFF1 + (c0 + 1) * 3 + u] = f.y;
        }
#pragma unroll
        for (int u = 0; u < 9; u++) {
            float2 f = unpk(acc2[j][u]);
            po[OFF2 + c0 * 9 + u] = f.x;
            po[OFF2 + (c0 + 1) * 9 + u] = f.y;
        }
    }
}

extern "C" void kernel_launch(void* const* d_in, const int* in_sizes, int n_in,
                              void* d_out, int out_size) {
    const float* x1 = (const float*)d_in[0];
    const float* x2 = (const float*)d_in[1];
    const float* w  = (const float*)d_in[2];
    float* out = (float*)d_out;

    // 1) transpose weights into k-major scratch
    wt_transpose_kernel<<<(WT_ELEMS + 255) / 256, 256>>>(w);

    // 2) main tensor-product kernel
    const int smem_bytes = (2 * Z_TILE * SROW + 2 * WROW) * (int)sizeof(float);
    static int attr_set = 0;
    if (!attr_set) {
        cudaFuncSetAttribute(tp_kernel, cudaFuncAttributeMaxDynamicSharedMemorySize, smem_bytes);
        attr_set = 1;
    }
    tp_kernel<<<NBLOCKS, 256, smem_bytes>>>(x1, x2, out);
}

// round 7
// speedup vs baseline: 1.2535x; 1.2535x over previous
#include <cuda_runtime.h>
#include <cuda_bf16.h>
#include <cstdint>

#define WTE (15 * 64 * 4096)

__device__ __align__(16) __nv_bfloat16 g_Whi[WTE];
__device__ __align__(16) __nv_bfloat16 g_Wlo[WTE];

// group of each path: 0 -> Lout0, 1 -> Lout1, 2 -> Lout2
__constant__ int c_grp[15] = {0,1,2,1,2,0,1,1,2,2,1,2,2,0,1};

// W scratch: tiles [p][a][c][b] bf16 hi/lo, from w[p][c][a][b]
__global__ void prep_w(const float* __restrict__ w) {
    int d = blockIdx.x * 256 + threadIdx.x;
    if (d >= WTE) return;
    int p = d >> 18, a = (d >> 12) & 63, c = (d >> 6) & 63, b = d & 63;
    float f = w[(p << 18) | (c << 12) | (a << 6) | b];
    __nv_bfloat16 hi = __float2bfloat16(f);
    g_Whi[d] = hi;
    g_Wlo[d] = __float2bfloat16(f - __bfloat162float(hi));
}

// ---------- smem byte layout (total 167424) ----------
#define X1_OFF   0        // 14*833*4 = 46648 (pad to 46656)
#define X2T_OFF  46656    // 14*840*4 = 47040
#define PHI_OFF  93696    // 128*72*2 = 18432
#define PLO_OFF  112128   // 18432
#define W_OFF    130560   // 2 bufs * 2 halves * 64 * 144 = 36864
#define SMEM_TOT 167424

__device__ __forceinline__ uint32_t smem_u32(const void* p) {
    uint32_t a;
    asm("{ .reg .u64 t; cvta.to.shared.u64 t, %1; cvt.u32.u64 %0, t; }" : "=r"(a) : "l"(p));
    return a;
}
__device__ __forceinline__ uint32_t pk2(__nv_bfloat16 a, __nv_bfloat16 b) {
    __nv_bfloat162 t(a, b);
    return *(uint32_t*)&t;
}
__device__ __forceinline__ uint32_t cvt2(float lo, float hi) {
    uint32_t r;
    asm("cvt.rn.bf16x2.f32 %0, %1, %2;" : "=r"(r) : "f"(hi), "f"(lo));
    return r;
}

#define LDSM4(r, addr) asm volatile( \
    "ldmatrix.sync.aligned.m8n8.x4.shared.b16 {%0,%1,%2,%3}, [%4];" \
    : "=r"((r)[0]), "=r"((r)[1]), "=r"((r)[2]), "=r"((r)[3]) : "r"(addr))

#define MMAB(d, a, bb0, bb1) asm volatile( \
    "mma.sync.aligned.m16n8k16.row.col.f32.bf16.bf16.f32 " \
    "{%0,%1,%2,%3}, {%4,%5,%6,%7}, {%8,%9}, {%0,%1,%2,%3};" \
    : "+f"((d)[0]), "+f"((d)[1]), "+f"((d)[2]), "+f"((d)[3]) \
    : "r"((a)[0]), "r"((a)[1]), "r"((a)[2]), "r"((a)[3]), "r"(bb0), "r"(bb1))

template<int MF>
__device__ __forceinline__ void warp_mma(float acc[][4][4], int m0, int n0,
                                         uint32_t pPhi, uint32_t pPlo,
                                         uint32_t pWh, uint32_t pWl, int lane) {
    const uint32_t aoff = (uint32_t)((lane & 15) * 144 + ((lane >> 4) << 4));
    const uint32_t boff = (uint32_t)(((lane & 7) + ((lane >> 4) & 1) * 8) * 144 + (lane & 8) * 2);
#pragma unroll
    for (int ks = 0; ks < 4; ks++) {
        const uint32_t kb = ks * 32;
        uint32_t ah[MF][4], al[MF][4];
#pragma unroll
        for (int mi = 0; mi < MF; mi++) {
            uint32_t o = (uint32_t)((m0 + mi * 16) * 144) + kb + aoff;
            LDSM4(ah[mi], pPhi + o);
            LDSM4(al[mi], pPlo + o);
        }
        uint32_t bh[8], bl[8];
#pragma unroll
        for (int nj = 0; nj < 2; nj++) {
            uint32_t o = (uint32_t)((n0 + nj * 16) * 144) + kb + boff;
            LDSM4(bh + nj * 4, pWh + o);
            LDSM4(bl + nj * 4, pWl + o);
        }
#pragma unroll
        for (int mi = 0; mi < MF; mi++)
#pragma unroll
            for (int ni = 0; ni < 4; ni++) {
                int ix = (ni >> 1) * 4 + (ni & 1) * 2;
                MMAB(acc[mi][ni], ah[mi], bh[ix], bh[ix + 1]);
                MMAB(acc[mi][ni], al[mi], bh[ix], bh[ix + 1]);
                MMAB(acc[mi][ni], ah[mi], bl[ix], bl[ix + 1]);
            }
    }
}

__device__ __forceinline__ void prefetch_w(int p, int a, int buf, uint32_t sb, int tid) {
    const size_t tile = ((size_t)(p * 64 + a)) << 12;
#pragma unroll
    for (int q = 0; q < 4; q++) {
        int i = tid + 256 * q;
        int half = i >> 9, r = i & 511;
        int cR = r >> 3, seg = r & 7;
        const __nv_bfloat16* src = (half ? g_Wlo : g_Whi) + tile + cR * 64 + seg * 8;
        uint32_t dst = sb + W_OFF + buf * 18432 + (half * 64 + cR) * 144 + seg * 16;
        asm volatile("cp.async.cg.shared.global [%0], [%1], 16;" :: "r"(dst), "l"(src));
    }
}

#define G8(nm, off) float nm[8]; { const float4* q_ = (const float4*)(bz + (off) + b0); \
    float4 t0_ = q_[0], t1_ = q_[1]; nm[0]=t0_.x; nm[1]=t0_.y; nm[2]=t0_.z; nm[3]=t0_.w; \
    nm[4]=t1_.x; nm[5]=t1_.y; nm[6]=t1_.z; nm[7]=t1_.w; }

__device__ __forceinline__ void gen_chunk(int p, int g, int a, int nzv,
                                          const float* smemf, char* smemc, int tid) {
    const int tasks = (g == 2) ? 1024 : (g == 1 ? 384 : 128);
    for (int t = tid; t < tasks; t += 256) {
        const int row = t >> 3;
        const int b0 = (t & 7) << 3;
        int z, u;
        if (g == 2)      { z = row / 9; u = row - z * 9; }
        else if (g == 1) { z = row / 3; u = row - z * 3; }
        else             { z = row;     u = 0; }
        if (z > nzv - 1) z = nzv - 1;
        const float* ax = smemf + z * 833;
        const float* bz = smemf + 11664 + z * 840;
        float v[8];
        switch (p) {
        case 0: { G8(s, 0); float A = ax[a];
#pragma unroll
            for (int j = 0; j < 8; j++) v[j] = A * s[j]; } break;
        case 1: { G8(s, 64 + u * 64); float A = ax[a];
#pragma unroll
            for (int j = 0; j < 8; j++) v[j] = A * s[j]; } break;
        case 2: { G8(s, 256 + u * 64); float A = ax[a];
#pragma unroll
            for (int j = 0; j < 8; j++) v[j] = A * s[j]; } break;
        case 3: { G8(s, 0); float A = ax[64 + 3 * a + u];
#pragma unroll
            for (int j = 0; j < 8; j++) v[j] = A * s[j]; } break;
        case 4: { G8(s, 64 + (u % 3) * 64); float A = ax[64 + 3 * a + u / 3];
#pragma unroll
            for (int j = 0; j < 8; j++) v[j] = A * s[j]; } break;
        case 5: { G8(q0, 64); G8(q1, 128); G8(q2, 192);
            const float* av = ax + 64 + 3 * a;
#pragma unroll
            for (int j = 0; j < 8; j++)
                v[j] = fmaf(av[2], q2[j], fmaf(av[1], q1[j], av[0] * q0[j])); } break;
        case 6: { int u1 = (u + 1) % 3, u2 = (u + 2) % 3;
            G8(qa, 64 + u2 * 64); G8(qb, 64 + u1 * 64);
            const float* av = ax + 64 + 3 * a;
#pragma unroll
            for (int j = 0; j < 8; j++) v[j] = av[u1] * qa[j] - av[u2] * qb[j]; } break;
        case 7: { G8(q0, 256 + (3 * u) * 64); G8(q1, 256 + (3 * u + 1) * 64); G8(q2, 256 + (3 * u + 2) * 64);
            const float* av = ax + 64 + 3 * a;
#pragma unroll
            for (int j = 0; j < 8; j++)
                v[j] = fmaf(av[2], q2[j], fmaf(av[1], q1[j], av[0] * q0[j])); } break;
        case 8: { int e = u / 3, gg = u % 3, g1 = (gg + 1) % 3, g2 = (gg + 2) % 3;
            G8(qa, 256 + (3 * e + g2) * 64); G8(qb, 256 + (3 * e + g1) * 64);
            const float* av = ax + 64 + 3 * a;
#pragma unroll
            for (int j = 0; j < 8; j++) v[j] = av[g1] * qa[j] - av[g2] * qb[j]; } break;
        case 9: { G8(s, 0); float A = ax[256 + 9 * a + u];
#pragma unroll
            for (int j = 0; j < 8; j++) v[j] = A * s[j]; } break;
        case 10: { G8(q0, 64); G8(q1, 128); G8(q2, 192);
            const float* m = ax + 256 + 9 * a + 3 * u;
#pragma unroll
            for (int j = 0; j < 8; j++)
                v[j] = fmaf(m[2], q2[j], fmaf(m[1], q1[j], m[0] * q0[j])); } break;
        case 11: { int d = u / 3, gg = u % 3, g1 = (gg + 1) % 3, g2 = (gg + 2) % 3;
            G8(qa, 64 + g2 * 64); G8(qb, 64 + g1 * 64);
            const float* m = ax + 256 + 9 * a + 3 * d;
#pragma unroll
            for (int j = 0; j < 8; j++) v[j] = m[g1] * qa[j] - m[g2] * qb[j]; } break;
        case 12: { int d = u / 3, f = u % 3;
            const float* m = ax + 256 + 9 * a + 3 * d;
            G8(q0, 256 + (3 * f) * 64); G8(q1, 256 + (3 * f + 1) * 64); G8(q2, 256 + (3 * f + 2) * 64);
#pragma unroll
            for (int j = 0; j < 8; j++)
                v[j] = fmaf(m[2], q2[j], fmaf(m[1], q1[j], m[0] * q0[j])); } break;
        case 13: { const float* m = ax + 256 + 9 * a;
#pragma unroll
            for (int j = 0; j < 8; j++) v[j] = 0.f;
#pragma unroll
            for (int t2 = 0; t2 < 9; t2++) {
                const float4* q_ = (const float4*)(bz + 256 + t2 * 64 + b0);
                float4 a0 = q_[0], a1 = q_[1];
                float mm = m[t2];
                v[0] = fmaf(mm, a0.x, v[0]); v[1] = fmaf(mm, a0.y, v[1]);
                v[2] = fmaf(mm, a0.z, v[2]); v[3] = fmaf(mm, a0.w, v[3]);
                v[4] = fmaf(mm, a1.x, v[4]); v[5] = fmaf(mm, a1.y, v[5]);
                v[6] = fmaf(mm, a1.z, v[6]); v[7] = fmaf(mm, a1.w, v[7]);
            } } break;
        default: { int u1 = (u + 1) % 3, u2 = (u + 2) % 3;   // p14
            const float* m1 = ax + 256 + 9 * a + 3 * u1;
            const float* m2 = ax + 256 + 9 * a + 3 * u2;
#pragma unroll
            for (int j = 0; j < 8; j++) v[j] = 0.f;
#pragma unroll
            for (int i = 0; i < 3; i++) {
                const float4* qa_ = (const float4*)(bz + 256 + (3 * u2 + i) * 64 + b0);
                const float4* qb_ = (const float4*)(bz + 256 + (3 * u1 + i) * 64 + b0);
                float4 a0 = qa_[0], a1 = qa_[1], c0 = qb_[0], c1 = qb_[1];
                float f1 = m1[i], f2 = m2[i];
                v[0] += f1 * a0.x - f2 * c0.x; v[1] += f1 * a0.y - f2 * c0.y;
                v[2] += f1 * a0.z - f2 * c0.z; v[3] += f1 * a0.w - f2 * c0.w;
                v[4] += f1 * a1.x - f2 * c1.x; v[5] += f1 * a1.y - f2 * c1.y;
                v[6] += f1 * a1.z - f2 * c1.z; v[7] += f1 * a1.w - f2 * c1.w;
            } } break;
        }
        uint32_t hp[4], lp[4];
#pragma unroll
        for (int jj = 0; jj < 4; jj++) {
            float v0 = v[2 * jj], v1 = v[2 * jj + 1];
            __nv_bfloat16 h0 = __float2bfloat16(v0), h1 = __float2bfloat16(v1);
            hp[jj] = pk2(h0, h1);
            lp[jj] = cvt2(v0 - __bfloat162float(h0), v1 - __bfloat162float(h1));
        }
        const int eo = row * 144 + b0 * 2;
        *(uint4*)(smemc + PHI_OFF + eo) = make_uint4(hp[0], hp[1], hp[2], hp[3]);
        *(uint4*)(smemc + PLO_OFF + eo) = make_uint4(lp[0], lp[1], lp[2], lp[3]);
    }
}

__global__ void __launch_bounds__(256, 1)
tp_hmma_kernel(const float* __restrict__ x1, const float* __restrict__ x2,
               float* __restrict__ out) {
    extern __shared__ char smem[];
    float* smemf = (float*)smem;
    const int tid = threadIdx.x, w = tid >> 5, lane = tid & 31;
    const int z0 = blockIdx.x * 14;
    const int nzv = min(14, 4096 - z0);
    const uint32_t sb = smem_u32(smem);
    const uint32_t pPhi = sb + PHI_OFF, pPlo = sb + PLO_OFF;

    // stage x1 (natural, stride 833) and x2 (component-major, stride 840)
    for (int i = tid; i < 14 * 832; i += 256) {
        int z = i / 832, f = i - z * 832;
        int zg = z0 + z; if (zg > 4095) zg = 4095;
        smemf[z * 833 + f] = x1[(size_t)zg * 832 + f];
        float v2 = x2[(size_t)zg * 832 + f];
        int d;
        if (f < 64) d = f;
        else if (f < 256) { int g = f - 64; d = 64 + (g % 3) * 64 + g / 3; }
        else { int g = f - 256; d = 256 + (g % 9) * 64 + g / 9; }
        smemf[11664 + z * 840 + d] = v2;
    }

    float accL2[2][4][4], accL1[1][4][4], accL0[1][4][4];
#pragma unroll
    for (int mi = 0; mi < 2; mi++)
#pragma unroll
        for (int ni = 0; ni < 4; ni++)
#pragma unroll
            for (int di = 0; di < 4; di++) {
                accL2[mi][ni][di] = 0.f;
                if (mi == 0) { accL1[0][ni][di] = 0.f; accL0[0][ni][di] = 0.f; }
            }

    prefetch_w(0, 0, 0, sb, tid);
    asm volatile("cp.async.commit_group;" ::: "memory");

    for (int c = 0; c < 960; c++) {
        const int p = c >> 6, a = c & 63, buf = c & 1;
        const int g = c_grp[p];
        __syncthreads();   // prev mma done with sP and the buffer we're about to refill
        if (c + 1 < 960) prefetch_w((c + 1) >> 6, (c + 1) & 63, (c + 1) & 1, sb, tid);
        asm volatile("cp.async.commit_group;" ::: "memory");
        gen_chunk(p, g, a, nzv, smemf, smem, tid);
        asm volatile("cp.async.wait_group 1;" ::: "memory");
        __syncthreads();   // P + W(buf) visible to all
        const uint32_t pWh = sb + W_OFF + buf * 18432;
        const uint32_t pWl = pWh + 9216;
        if (g == 2) {
            warp_mma<2>(accL2, (w & 3) * 32, (w >> 2) * 32, pPhi, pPlo, pWh, pWl, lane);
        } else if (g == 1) {
            if (w < 6) warp_mma<1>(accL1, (w % 3) * 16, (w / 3) * 32, pPhi, pPlo, pWh, pWl, lane);
        } else {
            if (w < 2) warp_mma<1>(accL0, 0, w * 32, pPhi, pPlo, pWh, pWl, lane);
        }
    }

    // ---- epilogue: direct gmem stores (D frag: row=(l>>2)+8*(di>>1), col=2*(l&3)+(di&1)) ----
    {
        const int m0 = (w & 3) * 32, n0 = (w >> 2) * 32;
#pragma unroll
        for (int mi = 0; mi < 2; mi++)
#pragma unroll
            for (int ni = 0; ni < 4; ni++)
#pragma unroll
                for (int di = 0; di < 4; di++) {
                    int row = m0 + mi * 16 + (lane >> 2) + (di >> 1) * 8;
                    int col = n0 + ni * 8 + (lane & 3) * 2 + (di & 1);
                    if (row < 126) {
                        int z = row / 9, u = row - z * 9;
                        if (z < nzv)
                            out[(size_t)(z0 + z) * 832 + 256 + col * 9 + u] = accL2[mi][ni][di];
                    }
                }
    }
    if (w < 6) {
        const int m0 = (w % 3) * 16, n0 = (w / 3) * 32;
#pragma unroll
        for (int ni = 0; ni < 4; ni++)
#pragma unroll
            for (int di = 0; di < 4; di++) {
                int row = m0 + (lane >> 2) + (di >> 1) * 8;
                int col = n0 + ni * 8 + (lane & 3) * 2 + (di & 1);
                if (row < 42) {
                    int z = row / 3, u = row - z * 3;
                    if (z < nzv)
                        out[(size_t)(z0 + z) * 832 + 64 + col * 3 + u] = accL1[0][ni][di];
                }
            }
    }
    if (w < 2) {
        const int n0 = w * 32;
#pragma unroll
        for (int ni = 0; ni < 4; ni++)
#pragma unroll
            for (int di = 0; di < 4; di++) {
                int row = (lane >> 2) + (di >> 1) * 8;
                int col = n0 + ni * 8 + (lane & 3) * 2 + (di & 1);
                if (row < nzv)
                    out[(size_t)(z0 + row) * 832 + col] = accL0[0][ni][di];
            }
    }
}

extern "C" void kernel_launch(void* const* d_in, const int* in_sizes, int n_in,
                              void* d_out, int out_size) {
    const float* x1 = (const float*)d_in[0];
    const float* x2 = (const float*)d_in[1];
    const float* w  = (const float*)d_in[2];
    float* out = (float*)d_out;

    prep_w<<<(WTE + 255) / 256, 256>>>(w);

    static int attr_set = 0;
    if (!attr_set) {
        cudaFuncSetAttribute(tp_hmma_kernel, cudaFuncAttributeMaxDynamicSharedMemorySize, SMEM_TOT);
        attr_set = 1;
    }
    tp_hmma_kernel<<<293, 256, SMEM_TOT>>>(x1, x2, out);
}

// round 8
// speedup vs baseline: 1.3481x; 1.0755x over previous
#include <cuda_runtime.h>
#include <cuda_bf16.h>
#include <cstdint>

#define WTE (15 * 64 * 4096)

__device__ __align__(16) __nv_bfloat16 g_Whi[WTE];
__device__ __align__(16) __nv_bfloat16 g_Wlo[WTE];

// group of each path: 0 -> Lout0, 1 -> Lout1, 2 -> Lout2
__constant__ int c_grp[15] = {0,1,2,1,2,0,1,1,2,2,1,2,2,0,1};

// W scratch: tiles [p][a][c][b] bf16 hi/lo, from w[p][c][a][b]
__global__ void prep_w(const float* __restrict__ w) {
    int d = blockIdx.x * 256 + threadIdx.x;
    if (d >= WTE) return;
    int p = d >> 18, a = (d >> 12) & 63, c = (d >> 6) & 63, b = d & 63;
    float f = w[(p << 18) | (c << 12) | (a << 6) | b];
    __nv_bfloat16 hi = __float2bfloat16(f);
    g_Whi[d] = hi;
    g_Wlo[d] = __float2bfloat16(f - __bfloat162float(hi));
}

// ---------- smem byte layout ----------
// x1: 14*833*4 = 46648 (region 0..46656)
// x2T: 46656 + 14*840*4 = 47040 -> ends 93696
// P: 2 buffers, each (hi 18432 + lo 18432) = 36864 -> 73728, ends 167424
// W: 3 slots * 18432 = 55296 -> ends 222720
#define P_OFF    93696
#define P_STRIDE 36864
#define W_OFF    167424
#define W_STRIDE 18432
#define SMEM_TOT 222720

__device__ __forceinline__ uint32_t smem_u32(const void* p) {
    uint32_t a;
    asm("{ .reg .u64 t; cvta.to.shared.u64 t, %1; cvt.u32.u64 %0, t; }" : "=r"(a) : "l"(p));
    return a;
}
__device__ __forceinline__ uint32_t pk2(__nv_bfloat16 a, __nv_bfloat16 b) {
    __nv_bfloat162 t(a, b);
    return *(uint32_t*)&t;
}
__device__ __forceinline__ uint32_t cvt2(float lo, float hi) {
    uint32_t r;
    asm("cvt.rn.bf16x2.f32 %0, %1, %2;" : "=r"(r) : "f"(hi), "f"(lo));
    return r;
}

#define LDSM4(r, addr) asm volatile( \
    "ldmatrix.sync.aligned.m8n8.x4.shared.b16 {%0,%1,%2,%3}, [%4];" \
    : "=r"((r)[0]), "=r"((r)[1]), "=r"((r)[2]), "=r"((r)[3]) : "r"(addr))

#define MMAB(d, a, bb0, bb1) asm volatile( \
    "mma.sync.aligned.m16n8k16.row.col.f32.bf16.bf16.f32 " \
    "{%0,%1,%2,%3}, {%4,%5,%6,%7}, {%8,%9}, {%0,%1,%2,%3};" \
    : "+f"((d)[0]), "+f"((d)[1]), "+f"((d)[2]), "+f"((d)[3]) \
    : "r"((a)[0]), "r"((a)[1]), "r"((a)[2]), "r"((a)[3]), "r"(bb0), "r"(bb1))

template<int MF>
__device__ __forceinline__ void warp_mma(float acc[][4][4], int m0, int n0,
                                         uint32_t pPhi, uint32_t pPlo,
                                         uint32_t pWh, uint32_t pWl, int lane) {
    const uint32_t aoff = (uint32_t)((lane & 15) * 144 + ((lane >> 4) << 4));
    const uint32_t boff = (uint32_t)(((lane & 7) + ((lane >> 4) & 1) * 8) * 144 + (lane & 8) * 2);
#pragma unroll
    for (int ks = 0; ks < 4; ks++) {
        const uint32_t kb = ks * 32;
        uint32_t ah[MF][4], al[MF][4];
#pragma unroll
        for (int mi = 0; mi < MF; mi++) {
            uint32_t o = (uint32_t)((m0 + mi * 16) * 144) + kb + aoff;
            LDSM4(ah[mi], pPhi + o);
            LDSM4(al[mi], pPlo + o);
        }
        uint32_t bh[8], bl[8];
#pragma unroll
        for (int nj = 0; nj < 2; nj++) {
            uint32_t o = (uint32_t)((n0 + nj * 16) * 144) + kb + boff;
            LDSM4(bh + nj * 4, pWh + o);
            LDSM4(bl + nj * 4, pWl + o);
        }
#pragma unroll
        for (int mi = 0; mi < MF; mi++)
#pragma unroll
            for (int ni = 0; ni < 4; ni++) {
                int ix = (ni >> 1) * 4 + (ni & 1) * 2;
                MMAB(acc[mi][ni], ah[mi], bh[ix], bh[ix + 1]);
                MMAB(acc[mi][ni], al[mi], bh[ix], bh[ix + 1]);
                MMAB(acc[mi][ni], ah[mi], bl[ix], bl[ix + 1]);
            }
    }
}

__device__ __forceinline__ void prefetch_w(int p, int a, int slot, uint32_t sb, int tid) {
    const size_t tile = ((size_t)(p * 64 + a)) << 12;
#pragma unroll
    for (int q = 0; q < 4; q++) {
        int i = tid + 256 * q;
        int half = i >> 9, r = i & 511;
        int cR = r >> 3, seg = r & 7;
        const __nv_bfloat16* src = (half ? g_Wlo : g_Whi) + tile + cR * 64 + seg * 8;
        uint32_t dst = sb + W_OFF + slot * W_STRIDE + (half * 64 + cR) * 144 + seg * 16;
        asm volatile("cp.async.cg.shared.global [%0], [%1], 16;" :: "r"(dst), "l"(src));
    }
}

#define G8(nm, off) float nm[8]; { const float4* q_ = (const float4*)(bz + (off) + b0); \
    float4 t0_ = q_[0], t1_ = q_[1]; nm[0]=t0_.x; nm[1]=t0_.y; nm[2]=t0_.z; nm[3]=t0_.w; \
    nm[4]=t1_.x; nm[5]=t1_.y; nm[6]=t1_.z; nm[7]=t1_.w; }

__device__ __forceinline__ void gen_chunk(int p, int g, int a, int nzv,
                                          const float* smemf, char* smemc,
                                          uint32_t phi_off, int tid) {
    const int tasks = (g == 2) ? 1024 : (g == 1 ? 384 : 128);
    for (int t = tid; t < tasks; t += 256) {
        const int row = t >> 3;
        const int b0 = (t & 7) << 3;
        int z, u;
        if (g == 2)      { z = row / 9; u = row - z * 9; }
        else if (g == 1) { z = row / 3; u = row - z * 3; }
        else             { z = row;     u = 0; }
        if (z > nzv - 1) z = nzv - 1;
        const float* ax = smemf + z * 833;
        const float* bz = smemf + 11664 + z * 840;
        float v[8];
        switch (p) {
        case 0: { G8(s, 0); float A = ax[a];
#pragma unroll
            for (int j = 0; j < 8; j++) v[j] = A * s[j]; } break;
        case 1: { G8(s, 64 + u * 64); float A = ax[a];
#pragma unroll
            for (int j = 0; j < 8; j++) v[j] = A * s[j]; } break;
        case 2: { G8(s, 256 + u * 64); float A = ax[a];
#pragma unroll
            for (int j = 0; j < 8; j++) v[j] = A * s[j]; } break;
        case 3: { G8(s, 0); float A = ax[64 + 3 * a + u];
#pragma unroll
            for (int j = 0; j < 8; j++) v[j] = A * s[j]; } break;
        case 4: { G8(s, 64 + (u % 3) * 64); float A = ax[64 + 3 * a + u / 3];
#pragma unroll
            for (int j = 0; j < 8; j++) v[j] = A * s[j]; } break;
        case 5: { G8(q0, 64); G8(q1, 128); G8(q2, 192);
            const float* av = ax + 64 + 3 * a;
#pragma unroll
            for (int j = 0; j < 8; j++)
                v[j] = fmaf(av[2], q2[j], fmaf(av[1], q1[j], av[0] * q0[j])); } break;
        case 6: { int u1 = (u + 1) % 3, u2 = (u + 2) % 3;
            G8(qa, 64 + u2 * 64); G8(qb, 64 + u1 * 64);
            const float* av = ax + 64 + 3 * a;
#pragma unroll
            for (int j = 0; j < 8; j++) v[j] = av[u1] * qa[j] - av[u2] * qb[j]; } break;
        case 7: { G8(q0, 256 + (3 * u) * 64); G8(q1, 256 + (3 * u + 1) * 64); G8(q2, 256 + (3 * u + 2) * 64);
            const float* av = ax + 64 + 3 * a;
#pragma unroll
            for (int j = 0; j < 8; j++)
                v[j] = fmaf(av[2], q2[j], fmaf(av[1], q1[j], av[0] * q0[j])); } break;
        case 8: { int e = u / 3, gg = u % 3, g1 = (gg + 1) % 3, g2 = (gg + 2) % 3;
            G8(qa, 256 + (3 * e + g2) * 64); G8(qb, 256 + (3 * e + g1) * 64);
            const float* av = ax + 64 + 3 * a;
#pragma unroll
            for (int j = 0; j < 8; j++) v[j] = av[g1] * qa[j] - av[g2] * qb[j]; } break;
        case 9: { G8(s, 0); float A = ax[256 + 9 * a + u];
#pragma unroll
            for (int j = 0; j < 8; j++) v[j] = A * s[j]; } break;
        case 10: { G8(q0, 64); G8(q1, 128); G8(q2, 192);
            const float* m = ax + 256 + 9 * a + 3 * u;
#pragma unroll
            for (int j = 0; j < 8; j++)
                v[j] = fmaf(m[2], q2[j], fmaf(m[1], q1[j], m[0] * q0[j])); } break;
        case 11: { int d = u / 3, gg = u % 3, g1 = (gg + 1) % 3, g2 = (gg + 2) % 3;
            G8(qa, 64 + g2 * 64); G8(qb, 64 + g1 * 64);
            const float* m = ax + 256 + 9 * a + 3 * d;
#pragma unroll
            for (int j = 0; j < 8; j++) v[j] = m[g1] * qa[j] - m[g2] * qb[j]; } break;
        case 12: { int d = u / 3, f = u % 3;
            const float* m = ax + 256 + 9 * a + 3 * d;
            G8(q0, 256 + (3 * f) * 64); G8(q1, 256 + (3 * f + 1) * 64); G8(q2, 256 + (3 * f + 2) * 64);
#pragma unroll
            for (int j = 0; j < 8; j++)
                v[j] = fmaf(m[2], q2[j], fmaf(m[1], q1[j], m[0] * q0[j])); } break;
        case 13: { const float* m = ax + 256 + 9 * a;
#pragma unroll
            for (int j = 0; j < 8; j++) v[j] = 0.f;
#pragma unroll
            for (int t2 = 0; t2 < 9; t2++) {
                const float4* q_ = (const float4*)(bz + 256 + t2 * 64 + b0);
                float4 a0 = q_[0], a1 = q_[1];
                float mm = m[t2];
                v[0] = fmaf(mm, a0.x, v[0]); v[1] = fmaf(mm, a0.y, v[1]);
                v[2] = fmaf(mm, a0.z, v[2]); v[3] = fmaf(mm, a0.w, v[3]);
                v[4] = fmaf(mm, a1.x, v[4]); v[5] = fmaf(mm, a1.y, v[5]);
                v[6] = fmaf(mm, a1.z, v[6]); v[7] = fmaf(mm, a1.w, v[7]);
            } } break;
        default: { int u1 = (u + 1) % 3, u2 = (u + 2) % 3;   // p14
            const float* m1 = ax + 256 + 9 * a + 3 * u1;
            const float* m2 = ax + 256 + 9 * a + 3 * u2;
#pragma unroll
            for (int j = 0; j < 8; j++) v[j] = 0.f;
#pragma unroll
            for (int i = 0; i < 3; i++) {
                const float4* qa_ = (const float4*)(bz + 256 + (3 * u2 + i) * 64 + b0);
                const float4* qb_ = (const float4*)(bz + 256 + (3 * u1 + i) * 64 + b0);
                float4 a0 = qa_[0], a1 = qa_[1], c0 = qb_[0], c1 = qb_[1];
                float f1 = m1[i], f2 = m2[i];
                v[0] += f1 * a0.x - f2 * c0.x; v[1] += f1 * a0.y - f2 * c0.y;
                v[2] += f1 * a0.z - f2 * c0.z; v[3] += f1 * a0.w - f2 * c0.w;
                v[4] += f1 * a1.x - f2 * c1.x; v[5] += f1 * a1.y - f2 * c1.y;
                v[6] += f1 * a1.z - f2 * c1.z; v[7] += f1 * a1.w - f2 * c1.w;
            } } break;
        }
        uint32_t hp[4], lp[4];
#pragma unroll
        for (int jj = 0; jj < 4; jj++) {
            float v0 = v[2 * jj], v1 = v[2 * jj + 1];
            __nv_bfloat16 h0 = __float2bfloat16(v0), h1 = __float2bfloat16(v1);
            hp[jj] = pk2(h0, h1);
            lp[jj] = cvt2(v0 - __bfloat162float(h0), v1 - __bfloat162float(h1));
        }
        const uint32_t eo = phi_off + row * 144 + b0 * 2;
        *(uint4*)(smemc + eo) = make_uint4(hp[0], hp[1], hp[2], hp[3]);
        *(uint4*)(smemc + eo + 18432) = make_uint4(lp[0], lp[1], lp[2], lp[3]);
    }
}

__global__ void __launch_bounds__(256, 1)
tp_hmma_kernel(const float* __restrict__ x1, const float* __restrict__ x2,
               float* __restrict__ out) {
    extern __shared__ char smem[];
    float* smemf = (float*)smem;
    const int tid = threadIdx.x, w = tid >> 5, lane = tid & 31;
    const int z0 = blockIdx.x * 14;
    const int nzv = min(14, 4096 - z0);
    const uint32_t sb = smem_u32(smem);

    // stage x1 (natural, stride 833) and x2 (component-major, stride 840)
    for (int i = tid; i < 14 * 832; i += 256) {
        int z = i / 832, f = i - z * 832;
        int zg = z0 + z; if (zg > 4095) zg = 4095;
        smemf[z * 833 + f] = x1[(size_t)zg * 832 + f];
        float v2 = x2[(size_t)zg * 832 + f];
        int d;
        if (f < 64) d = f;
        else if (f < 256) { int g = f - 64; d = 64 + (g % 3) * 64 + g / 3; }
        else { int g = f - 256; d = 256 + (g % 9) * 64 + g / 9; }
        smemf[11664 + z * 840 + d] = v2;
    }

    float accL2[2][4][4], accL1[1][4][4], accL0[1][4][4];
#pragma unroll
    for (int mi = 0; mi < 2; mi++)
#pragma unroll
        for (int ni = 0; ni < 4; ni++)
#pragma unroll
            for (int di = 0; di < 4; di++) {
                accL2[mi][ni][di] = 0.f;
                if (mi == 0) { accL1[0][ni][di] = 0.f; accL0[0][ni][di] = 0.f; }
            }

    // prologue: W0, W1 in flight; gen chunk0; wait W0; publish
    prefetch_w(0, 0, 0, sb, tid);
    asm volatile("cp.async.commit_group;" ::: "memory");
    prefetch_w(0, 1, 1, sb, tid);
    asm volatile("cp.async.commit_group;" ::: "memory");
    __syncthreads();                        // staging visible for gen
    gen_chunk(0, c_grp[0], 0, nzv, smemf, smem, P_OFF, tid);
    asm volatile("cp.async.wait_group 1;" ::: "memory");   // W0 done
    __syncthreads();                        // publish P0 + W0

    // invariant at top of iter c: P[c&1] + W[c] visible to all; W[c+1] in flight
    for (int c = 0; c < 960; c++) {
        const int cn = c + 2;
        if (cn < 960) prefetch_w(cn >> 6, cn & 63, cn % 3, sb, tid);
        asm volatile("cp.async.commit_group;" ::: "memory");
        const int cg = c + 1;
        if (cg < 960)
            gen_chunk(cg >> 6, c_grp[cg >> 6], cg & 63, nzv, smemf, smem,
                      P_OFF + (cg & 1) * P_STRIDE, tid);
        asm volatile("cp.async.wait_group 1;" ::: "memory");   // W[c+1] landed
        // mma chunk c (overlaps gen above at issue level; no barrier between)
        const int g = c_grp[c >> 6];
        const uint32_t pP = sb + P_OFF + (c & 1) * P_STRIDE;
        const uint32_t pWh = sb + W_OFF + (c % 3) * W_STRIDE;
        const uint32_t pWl = pWh + 9216;
        if (g == 2) {
            warp_mma<2>(accL2, (w & 3) * 32, (w >> 2) * 32, pP, pP + 18432, pWh, pWl, lane);
        } else if (g == 1) {
            if (w < 6) warp_mma<1>(accL1, (w % 3) * 16, (w / 3) * 32, pP, pP + 18432, pWh, pWl, lane);
        } else {
            if (w < 2) warp_mma<1>(accL0, 0, w * 32, pP, pP + 18432, pWh, pWl, lane);
        }
        __syncthreads();   // publish P[(c+1)&1] and W[c+1]; retire readers of P[c&1], W slot
    }

    // ---- epilogue: direct gmem stores (D frag: row=(l>>2)+8*(di>>1), col=2*(l&3)+(di&1)) ----
    {
        const int m0 = (w & 3) * 32, n0 = (w >> 2) * 32;
#pragma unroll
        for (int mi = 0; mi < 2; mi++)
#pragma unroll
            for (int ni = 0; ni < 4; ni++)
#pragma unroll
                for (int di = 0; di < 4; di++) {
                    int row = m0 + mi * 16 + (lane >> 2) + (di >> 1) * 8;
                    int col = n0 + ni * 8 + (lane & 3) * 2 + (di & 1);
                    if (row < 126) {
                        int z = row / 9, u = row - z * 9;
                        if (z < nzv)
                            out[(size_t)(z0 + z) * 832 + 256 + col * 9 + u] = accL2[mi][ni][di];
                    }
                }
    }
    if (w < 6) {
        const int m0 = (w % 3) * 16, n0 = (w / 3) * 32;
#pragma unroll
        for (int ni = 0; ni < 4; ni++)
#pragma unroll
            for (int di = 0; di < 4; di++) {
                int row = m0 + (lane >> 2) + (di >> 1) * 8;
                int col = n0 + ni * 8 + (lane & 3) * 2 + (di & 1);
                if (row < 42) {
                    int z = row / 3, u = row - z * 3;
                    if (z < nzv)
                        out[(size_t)(z0 + z) * 832 + 64 + col * 3 + u] = accL1[0][ni][di];
                }
            }
    }
    if (w < 2) {
        const int n0 = w * 32;
#pragma unroll
        for (int ni = 0; ni < 4; ni++)
#pragma unroll
            for (int di = 0; di < 4; di++) {
                int row = (lane >> 2) + (di >> 1) * 8;
                int col = n0 + ni * 8 + (lane & 3) * 2 + (di & 1);
                if (row < nzv)
                    out[(size_t)(z0 + row) * 832 + col] = accL0[0][ni][di];
            }
    }
}

extern "C" void kernel_launch(void* const* d_in, const int* in_sizes, int n_in,
                              void* d_out, int out_size) {
    const float* x1 = (const float*)d_in[0];
    const float* x2 = (const float*)d_in[1];
    const float* w  = (const float*)d_in[2];
    float* out = (float*)d_out;

    prep_w<<<(WTE + 255) / 256, 256>>>(w);

    static int attr_set = 0;
    if (!attr_set) {
        cudaFuncSetAttribute(tp_hmma_kernel, cudaFuncAttributeMaxDynamicSharedMemorySize, SMEM_TOT);
        attr_set = 1;
    }
    tp_hmma_kernel<<<293, 256, SMEM_TOT>>>(x1, x2, out);
}